// round 1
// baseline (speedup 1.0000x reference)
#include <cuda_runtime.h>
#include <math.h>

// Problem constants (fixed shapes)
#define BATCH 128
#define TT    32
#define DD    128
#define HH    256
#define OO    128
#define ZZ    384   // D + H

// Tiling
#define RB       16   // rows per block
#define BBATCH   8    // batches per block
#define NTHREADS 256

// Ping-pong hidden-state scratch (allocation-free: __device__ global)
__device__ float g_hbuf[2][BATCH * HH];

// One recurrent timestep, fused: for each (batch b, row r):
//   pre = (W[r,:] + F[b,r,:]) . z_b + bias[r]
//   h   = tanh(pre)
//   F[b,r,:] = lam[r,:]*F[b,r,:] + gamma[r,:]*h*z_b
// F read exactly once, written exactly once.
__global__ __launch_bounds__(NTHREADS)
void stpn_step_kernel(int t,
                      const float* __restrict__ x,       // [B,T,D]
                      const float* __restrict__ h_prev,  // [B,H]
                      float* __restrict__ h_new,         // [B,H]
                      const float* __restrict__ F_in,    // [B,H,Z]
                      float* __restrict__ F_out,         // [B,H,Z] (may alias F_in)
                      const float* __restrict__ W,       // [H,Z]
                      const float* __restrict__ bias,    // [H]
                      const float* __restrict__ lam,     // [H,Z]
                      const float* __restrict__ gam)     // [H,Z]
{
    __shared__ __align__(16) float zsh[BBATCH][ZZ];

    const int tid  = threadIdx.x;
    const int row0 = blockIdx.x * RB;
    const int b0   = blockIdx.y * BBATCH;

    // Stage z = [x_t ; h_prev] for BBATCH batches into SMEM
    for (int idx = tid; idx < BBATCH * ZZ; idx += NTHREADS) {
        int j = idx / ZZ;
        int c = idx - j * ZZ;
        float v;
        if (c < DD) v = x[((size_t)(b0 + j) * TT + t) * DD + c];
        else        v = h_prev[(size_t)(b0 + j) * HH + (c - DD)];
        zsh[j][c] = v;
    }
    __syncthreads();

    const int warp = tid >> 5;
    const int lane = tid & 31;

    #pragma unroll
    for (int rr = 0; rr < RB; rr += 8) {
        const int r = row0 + rr + warp;

        // Per-row parameters held in registers, reused across all 8 batches
        const float4* Wr = reinterpret_cast<const float4*>(W   + (size_t)r * ZZ);
        const float4* Lr = reinterpret_cast<const float4*>(lam + (size_t)r * ZZ);
        const float4* Gr = reinterpret_cast<const float4*>(gam + (size_t)r * ZZ);
        float4 w0 = Wr[lane], w1 = Wr[lane + 32], w2 = Wr[lane + 64];
        float4 l0 = Lr[lane], l1 = Lr[lane + 32], l2 = Lr[lane + 64];
        float4 g0 = Gr[lane], g1 = Gr[lane + 32], g2 = Gr[lane + 64];
        const float bi = bias[r];

        #pragma unroll 2
        for (int j = 0; j < BBATCH; j++) {
            const size_t off = ((size_t)(b0 + j) * HH + r) * ZZ;
            const float4* Fr = reinterpret_cast<const float4*>(F_in  + off);
            float4*       Fw = reinterpret_cast<float4*>      (F_out + off);

            float4 f0 = Fr[lane], f1 = Fr[lane + 32], f2 = Fr[lane + 64];

            const float4* zj = reinterpret_cast<const float4*>(zsh[j]);
            float4 z0 = zj[lane], z1 = zj[lane + 32], z2 = zj[lane + 64];

            float dot =
                (w0.x + f0.x) * z0.x + (w0.y + f0.y) * z0.y +
                (w0.z + f0.z) * z0.z + (w0.w + f0.w) * z0.w +
                (w1.x + f1.x) * z1.x + (w1.y + f1.y) * z1.y +
                (w1.z + f1.z) * z1.z + (w1.w + f1.w) * z1.w +
                (w2.x + f2.x) * z2.x + (w2.y + f2.y) * z2.y +
                (w2.z + f2.z) * z2.z + (w2.w + f2.w) * z2.w;

            // butterfly reduce -> every lane holds the full dot
            dot += __shfl_xor_sync(0xffffffffu, dot, 16);
            dot += __shfl_xor_sync(0xffffffffu, dot, 8);
            dot += __shfl_xor_sync(0xffffffffu, dot, 4);
            dot += __shfl_xor_sync(0xffffffffu, dot, 2);
            dot += __shfl_xor_sync(0xffffffffu, dot, 1);

            const float hn = tanhf(dot + bi);

            // Hebbian fast-weight update
            f0.x = l0.x * f0.x + g0.x * hn * z0.x;
            f0.y = l0.y * f0.y + g0.y * hn * z0.y;
            f0.z = l0.z * f0.z + g0.z * hn * z0.z;
            f0.w = l0.w * f0.w + g0.w * hn * z0.w;
            f1.x = l1.x * f1.x + g1.x * hn * z1.x;
            f1.y = l1.y * f1.y + g1.y * hn * z1.y;
            f1.z = l1.z * f1.z + g1.z * hn * z1.z;
            f1.w = l1.w * f1.w + g1.w * hn * z1.w;
            f2.x = l2.x * f2.x + g2.x * hn * z2.x;
            f2.y = l2.y * f2.y + g2.y * hn * z2.y;
            f2.z = l2.z * f2.z + g2.z * hn * z2.z;
            f2.w = l2.w * f2.w + g2.w * hn * z2.w;

            Fw[lane]      = f0;
            Fw[lane + 32] = f1;
            Fw[lane + 64] = f2;

            if (lane == 0) h_new[(size_t)(b0 + j) * HH + r] = hn;
        }
    }
}

// tag_space = h_final @ W_out^T + b_out   (tiny: 8.4 MFLOP)
__global__ __launch_bounds__(OO)
void tag_head_kernel(const float* __restrict__ h,     // [B,H]
                     const float* __restrict__ Wout,  // [O,H]
                     const float* __restrict__ bout,  // [O]
                     float* __restrict__ tag)         // [B,O]
{
    __shared__ float hsh[HH];
    const int b = blockIdx.x;
    const int o = threadIdx.x;

    for (int i = threadIdx.x; i < HH; i += OO) hsh[i] = h[(size_t)b * HH + i];
    __syncthreads();

    float acc = bout[o];
    const float* wr = Wout + (size_t)o * HH;
    #pragma unroll 8
    for (int k = 0; k < HH; k++) acc += wr[k] * hsh[k];
    tag[(size_t)b * OO + o] = acc;
}

extern "C" void kernel_launch(void* const* d_in, const int* in_sizes, int n_in,
                              void* d_out, int out_size)
{
    const float* x     = (const float*)d_in[0];  // sentence [B,T,D]
    const float* h0    = (const float*)d_in[1];  // [B,H]
    const float* F0    = (const float*)d_in[2];  // [B,H,Z]
    const float* W     = (const float*)d_in[3];  // [H,Z]
    const float* bias  = (const float*)d_in[4];  // [H]
    const float* lam   = (const float*)d_in[5];  // [H,Z]
    const float* gam   = (const float*)d_in[6];  // [H,Z]
    const float* Wout  = (const float*)d_in[7];  // [O,H]
    const float* bout  = (const float*)d_in[8];  // [O]

    // Output layout assumption: concat(tag_space [B,O], h [B,H], F [B,H,Z])
    float* out   = (float*)d_out;
    float* tag   = out;
    float* h_out = out + (size_t)BATCH * OO;
    float* F_out = out + (size_t)BATCH * OO + (size_t)BATCH * HH;

    float* hbuf0;
    float* hbuf1;
    cudaGetSymbolAddress((void**)&hbuf0, g_hbuf);
    hbuf1 = hbuf0 + BATCH * HH;

    dim3 grid(HH / RB, BATCH / BBATCH);   // 16 x 16 = 256 blocks

    for (int t = 0; t < TT; t++) {
        const float* hp = (t == 0) ? h0 : ((t - 1) & 1 ? hbuf1 : hbuf0);
        float*       hn = (t == TT - 1) ? h_out : ((t & 1) ? hbuf1 : hbuf0);
        const float* Fi = (t == 0) ? F0 : F_out;   // step 0 reads F0, writes F_out; then in-place
        stpn_step_kernel<<<grid, NTHREADS>>>(t, x, hp, hn, Fi, F_out,
                                             W, bias, lam, gam);
    }

    tag_head_kernel<<<BATCH, OO>>>(h_out, Wout, bout, tag);
}

// round 2
// speedup vs baseline: 1.0862x; 1.0862x over previous
#include <cuda_runtime.h>
#include <math.h>

// Problem constants (fixed shapes)
#define BATCH 128
#define TT    32
#define DD    128
#define HH    256
#define OO    128
#define ZZ    384   // D + H

#define NTHREADS 256
#define NWARPS   8     // rows per block (1 row per warp, fixed for all t)
#define NB       16    // batches per block
#define NROWG    32    // 256 rows / 8
#define NBATG    8     // 128 batches / 16
#define NBLOCKS  (NROWG * NBATG)   // 256 blocks; single wave (<= 2*148)

// Ping-pong hidden-state scratch + grid-barrier counter (allocation-free)
__device__ float g_hbuf[2][BATCH * HH];
__device__ unsigned int g_bar;

// Persistent kernel: runs all 32 timesteps. Warp w of block owns row
// r = rowgroup*8 + w for the whole sequence -> W/lam/gamma row lives in
// registers across ALL steps and ALL batches. Per step, warp streams F rows
// for its 16 batches (read once, write once). Cross-block h exchange via
// global ping-pong buffer + single-wave grid barrier.
__global__ __launch_bounds__(NTHREADS, 2)
void stpn_persistent(const float* __restrict__ x,     // [B,T,D]
                     const float* __restrict__ h0,    // [B,H]
                     const float* __restrict__ F0,    // [B,H,Z]
                     float* F_out,                    // [B,H,Z] (in-place after step 0)
                     const float* __restrict__ W,     // [H,Z]
                     const float* __restrict__ bias,  // [H]
                     const float* __restrict__ lam,   // [H,Z]
                     const float* __restrict__ gam,   // [H,Z]
                     float* __restrict__ h_out)       // [B,H]
{
    __shared__ __align__(16) float zsh[NB][ZZ];   // 24 KB

    const int tid  = threadIdx.x;
    const int warp = tid >> 5;
    const int lane = tid & 31;
    const int rowg = blockIdx.x & (NROWG - 1);
    const int batg = blockIdx.x >> 5;
    const int r    = rowg * NWARPS + warp;
    const int b0   = batg * NB;

    // Slow-weight parameters for this warp's row: loaded ONCE, reused 32*16 times
    const float4* Wr = reinterpret_cast<const float4*>(W   + (size_t)r * ZZ);
    const float4* Lr = reinterpret_cast<const float4*>(lam + (size_t)r * ZZ);
    const float4* Gr = reinterpret_cast<const float4*>(gam + (size_t)r * ZZ);
    const float4 w0 = Wr[lane], w1 = Wr[lane + 32], w2 = Wr[lane + 64];
    const float4 l0 = Lr[lane], l1 = Lr[lane + 32], l2 = Lr[lane + 64];
    const float4 g0 = Gr[lane], g1 = Gr[lane + 32], g2 = Gr[lane + 64];
    const float  bi = bias[r];

    for (int t = 0; t < TT; t++) {
        // ---- stage z = [x_t ; h_prev] for this block's 16 batches ----
        const float* hp = (t == 0) ? h0 : g_hbuf[(t - 1) & 1];
        for (int idx = tid; idx < NB * ZZ; idx += NTHREADS) {
            int j = idx / ZZ;
            int c = idx - j * ZZ;
            float v;
            if (c < DD) v = x[((size_t)(b0 + j) * TT + t) * DD + c];
            else        v = __ldcg(&hp[(size_t)(b0 + j) * HH + (c - DD)]);  // L2: cross-SM producer
            zsh[j][c] = v;
        }
        __syncthreads();

        const float* Fi = (t == 0) ? F0 : F_out;
        float* hw = g_hbuf[t & 1];

        #pragma unroll 2
        for (int j = 0; j < NB; j++) {
            const size_t off = ((size_t)(b0 + j) * HH + r) * ZZ;
            const float4* Fr = reinterpret_cast<const float4*>(Fi + off);
            float4*       Fw = reinterpret_cast<float4*>(F_out + off);

            float4 f0 = Fr[lane], f1 = Fr[lane + 32], f2 = Fr[lane + 64];

            const float4* zj = reinterpret_cast<const float4*>(zsh[j]);
            float4 z0 = zj[lane], z1 = zj[lane + 32], z2 = zj[lane + 64];

            float dot =
                (w0.x + f0.x) * z0.x + (w0.y + f0.y) * z0.y +
                (w0.z + f0.z) * z0.z + (w0.w + f0.w) * z0.w +
                (w1.x + f1.x) * z1.x + (w1.y + f1.y) * z1.y +
                (w1.z + f1.z) * z1.z + (w1.w + f1.w) * z1.w +
                (w2.x + f2.x) * z2.x + (w2.y + f2.y) * z2.y +
                (w2.z + f2.z) * z2.z + (w2.w + f2.w) * z2.w;

            dot += __shfl_xor_sync(0xffffffffu, dot, 16);
            dot += __shfl_xor_sync(0xffffffffu, dot, 8);
            dot += __shfl_xor_sync(0xffffffffu, dot, 4);
            dot += __shfl_xor_sync(0xffffffffu, dot, 2);
            dot += __shfl_xor_sync(0xffffffffu, dot, 1);

            const float hn = tanhf(dot + bi);

            f0.x = l0.x * f0.x + g0.x * hn * z0.x;
            f0.y = l0.y * f0.y + g0.y * hn * z0.y;
            f0.z = l0.z * f0.z + g0.z * hn * z0.z;
            f0.w = l0.w * f0.w + g0.w * hn * z0.w;
            f1.x = l1.x * f1.x + g1.x * hn * z1.x;
            f1.y = l1.y * f1.y + g1.y * hn * z1.y;
            f1.z = l1.z * f1.z + g1.z * hn * z1.z;
            f1.w = l1.w * f1.w + g1.w * hn * z1.w;
            f2.x = l2.x * f2.x + g2.x * hn * z2.x;
            f2.y = l2.y * f2.y + g2.y * hn * z2.y;
            f2.z = l2.z * f2.z + g2.z * hn * z2.z;
            f2.w = l2.w * f2.w + g2.w * hn * z2.w;

            Fw[lane]      = f0;
            Fw[lane + 32] = f1;
            Fw[lane + 64] = f2;

            if (lane == 0) {
                hw[(size_t)(b0 + j) * HH + r] = hn;
                if (t == TT - 1) h_out[(size_t)(b0 + j) * HH + r] = hn;
            }
        }

        if (t == TT - 1) break;   // no barrier needed after last step

        // ---- single-wave grid barrier (release: fence-all then arrive) ----
        __threadfence();
        __syncthreads();
        if (tid == 0) {
            atomicAdd(&g_bar, 1u);
            const unsigned int target = (unsigned int)(t + 1) * NBLOCKS;
            while (*((volatile unsigned int*)&g_bar) < target) {
                __nanosleep(64);
            }
        }
        __syncthreads();   // also protects zsh reuse next iteration
    }
}

// tag_space = h_final @ W_out^T + b_out
__global__ __launch_bounds__(OO)
void tag_head_kernel(const float* __restrict__ h,     // [B,H]
                     const float* __restrict__ Wout,  // [O,H]
                     const float* __restrict__ bout,  // [O]
                     float* __restrict__ tag)         // [B,O]
{
    __shared__ float hsh[HH];
    const int b = blockIdx.x;
    const int o = threadIdx.x;

    for (int i = threadIdx.x; i < HH; i += OO) hsh[i] = h[(size_t)b * HH + i];
    __syncthreads();

    float acc = bout[o];
    const float* wr = Wout + (size_t)o * HH;
    #pragma unroll 8
    for (int k = 0; k < HH; k++) acc += wr[k] * hsh[k];
    tag[(size_t)b * OO + o] = acc;
}

extern "C" void kernel_launch(void* const* d_in, const int* in_sizes, int n_in,
                              void* d_out, int out_size)
{
    const float* x     = (const float*)d_in[0];  // sentence [B,T,D]
    const float* h0    = (const float*)d_in[1];  // [B,H]
    const float* F0    = (const float*)d_in[2];  // [B,H,Z]
    const float* W     = (const float*)d_in[3];  // [H,Z]
    const float* bias  = (const float*)d_in[4];  // [H]
    const float* lam   = (const float*)d_in[5];  // [H,Z]
    const float* gam   = (const float*)d_in[6];  // [H,Z]
    const float* Wout  = (const float*)d_in[7];  // [O,H]
    const float* bout  = (const float*)d_in[8];  // [O]

    // Output layout: concat(tag_space [B,O], h [B,H], F [B,H,Z])
    float* out   = (float*)d_out;
    float* tag   = out;
    float* h_out = out + (size_t)BATCH * OO;
    float* F_out = out + (size_t)BATCH * OO + (size_t)BATCH * HH;

    // Reset grid-barrier counter (async memset is graph-capturable)
    void* bar_ptr = nullptr;
    cudaGetSymbolAddress(&bar_ptr, g_bar);
    cudaMemsetAsync(bar_ptr, 0, sizeof(unsigned int));

    stpn_persistent<<<NBLOCKS, NTHREADS>>>(x, h0, F0, F_out,
                                           W, bias, lam, gam, h_out);

    tag_head_kernel<<<BATCH, OO>>>(h_out, Wout, bout, tag);
}

// round 3
// speedup vs baseline: 1.3802x; 1.2707x over previous
#include <cuda_runtime.h>
#include <math.h>

// Problem constants (fixed shapes)
#define BATCH 128
#define TT    32
#define DD    128
#define HH    256
#define OO    128
#define ZZ    384   // D + H

#define NTHREADS 256
#define NWARPS   8     // rows per block (1 row per warp, fixed for all t)
#define NB       16    // batches per block
#define NROWG    32    // 256 rows / 8
#define NBATG    8     // 128 batches / 16
#define NBLOCKS  (NROWG * NBATG)   // 256 blocks; single wave (2/SM)

#define FSTRIDE4 ((HH * ZZ) / 4)   // float4 stride between batches in F

// Ping-pong hidden-state scratch + per-batch-group barrier counters
__device__ float g_hbuf[2][BATCH * HH];
__device__ unsigned int g_bar[NBATG * 32];   // one counter per 128B line

__device__ __forceinline__ float fast_tanh(float x) {
    float xc = fminf(fmaxf(x, -9.0f), 9.0f);
    float e  = __expf(2.0f * xc);
    return __fdividef(e - 1.0f, e + 1.0f);
}

__global__ __launch_bounds__(NTHREADS, 2)
void stpn_persistent(const float4* __restrict__ x4,   // [B,T,D]
                     const float4* __restrict__ h04,  // [B,H]
                     const float*  __restrict__ F0,   // [B,H,Z]
                     float* F_out,                    // [B,H,Z] (in-place after step 0)
                     const float* __restrict__ W,     // [H,Z]
                     const float* __restrict__ bias,  // [H]
                     const float* __restrict__ lam,   // [H,Z]
                     const float* __restrict__ gam,   // [H,Z]
                     float* __restrict__ h_out)       // [B,H]
{
    __shared__ __align__(16) float4 zsh4[NB * 96];   // 16 batches x 384 floats

    const int tid  = threadIdx.x;
    const int warp = tid >> 5;
    const int lane = tid & 31;
    const int rowg = blockIdx.x & (NROWG - 1);
    const int batg = blockIdx.x >> 5;
    const int r    = rowg * NWARPS + warp;
    const int b0   = batg * NB;

    // Slow-weight parameters for this warp's row: loaded ONCE for the whole run
    const float4* Wr = reinterpret_cast<const float4*>(W   + (size_t)r * ZZ);
    const float4* Lr = reinterpret_cast<const float4*>(lam + (size_t)r * ZZ);
    const float4* Gr = reinterpret_cast<const float4*>(gam + (size_t)r * ZZ);
    const float4 w0 = Wr[lane], w1 = Wr[lane + 32], w2 = Wr[lane + 64];
    const float4 l0 = Lr[lane], l1 = Lr[lane + 32], l2 = Lr[lane + 64];
    const float4 g0 = Gr[lane], g1 = Gr[lane + 32], g2 = Gr[lane + 64];
    const float  bi = bias[r];

    // Per-warp F base (float4): batch j row at  + j*FSTRIDE4
    const size_t fbase = ((size_t)b0 * HH + r) * (ZZ / 4);
    float4* Fw4 = reinterpret_cast<float4*>(F_out) + fbase;

    unsigned int* ctr = &g_bar[batg * 32];

    for (int t = 0; t < TT; t++) {
        // ---- stage z = [x_t ; h_prev] (vectorized) ----
        {
            // x part: NB batches x 32 float4
            for (int i = tid; i < NB * 32; i += NTHREADS) {
                int j = i >> 5, c = i & 31;
                zsh4[j * 96 + c] = x4[((size_t)(b0 + j) * TT + t) * 32 + c];
            }
            // h part: NB batches x 64 float4
            const float4* hp4 = (t == 0) ? h04
                              : reinterpret_cast<const float4*>(g_hbuf[(t - 1) & 1]);
            for (int i = tid; i < NB * 64; i += NTHREADS) {
                int j = i >> 6, c = i & 63;
                zsh4[j * 96 + 32 + c] = __ldcg(&hp4[(size_t)(b0 + j) * 64 + c]);
            }
        }
        __syncthreads();

        const float4* Fr4 = (t == 0)
            ? reinterpret_cast<const float4*>(F0) + fbase
            : reinterpret_cast<const float4*>(F_out) + fbase;
        float* hw = g_hbuf[t & 1];

        // prefetch batch pair 0/1
        float4 pa0 = Fr4[lane],                pa1 = Fr4[lane + 32],
               pa2 = Fr4[lane + 64];
        float4 pb0 = Fr4[FSTRIDE4 + lane],     pb1 = Fr4[FSTRIDE4 + lane + 32],
               pb2 = Fr4[FSTRIDE4 + lane + 64];

        #pragma unroll 1
        for (int jp = 0; jp < NB / 2; jp++) {
            const int ja = 2 * jp, jb = ja + 1;
            float4 fa0 = pa0, fa1 = pa1, fa2 = pa2;
            float4 fb0 = pb0, fb1 = pb1, fb2 = pb2;

            // prefetch next pair BEFORE this pair's stores (breaks alias serialization)
            if (jp < NB / 2 - 1) {
                const float4* na = Fr4 + (size_t)(ja + 2) * FSTRIDE4;
                const float4* nb = Fr4 + (size_t)(jb + 2) * FSTRIDE4;
                pa0 = na[lane]; pa1 = na[lane + 32]; pa2 = na[lane + 64];
                pb0 = nb[lane]; pb1 = nb[lane + 32]; pb2 = nb[lane + 64];
            }

            const float4* za = &zsh4[ja * 96];
            const float4* zb = &zsh4[jb * 96];
            float4 za0 = za[lane], za1 = za[lane + 32], za2 = za[lane + 64];
            float4 zb0 = zb[lane], zb1 = zb[lane + 32], zb2 = zb[lane + 64];

            float dotA =
                (w0.x + fa0.x) * za0.x + (w0.y + fa0.y) * za0.y +
                (w0.z + fa0.z) * za0.z + (w0.w + fa0.w) * za0.w +
                (w1.x + fa1.x) * za1.x + (w1.y + fa1.y) * za1.y +
                (w1.z + fa1.z) * za1.z + (w1.w + fa1.w) * za1.w +
                (w2.x + fa2.x) * za2.x + (w2.y + fa2.y) * za2.y +
                (w2.z + fa2.z) * za2.z + (w2.w + fa2.w) * za2.w;
            float dotB =
                (w0.x + fb0.x) * zb0.x + (w0.y + fb0.y) * zb0.y +
                (w0.z + fb0.z) * zb0.z + (w0.w + fb0.w) * zb0.w +
                (w1.x + fb1.x) * zb1.x + (w1.y + fb1.y) * zb1.y +
                (w1.z + fb1.z) * zb1.z + (w1.w + fb1.w) * zb1.w +
                (w2.x + fb2.x) * zb2.x + (w2.y + fb2.y) * zb2.y +
                (w2.z + fb2.z) * zb2.z + (w2.w + fb2.w) * zb2.w;

            // interleaved butterfly reductions (two independent chains)
            dotA += __shfl_xor_sync(0xffffffffu, dotA, 16);
            dotB += __shfl_xor_sync(0xffffffffu, dotB, 16);
            dotA += __shfl_xor_sync(0xffffffffu, dotA, 8);
            dotB += __shfl_xor_sync(0xffffffffu, dotB, 8);
            dotA += __shfl_xor_sync(0xffffffffu, dotA, 4);
            dotB += __shfl_xor_sync(0xffffffffu, dotB, 4);
            dotA += __shfl_xor_sync(0xffffffffu, dotA, 2);
            dotB += __shfl_xor_sync(0xffffffffu, dotB, 2);
            dotA += __shfl_xor_sync(0xffffffffu, dotA, 1);
            dotB += __shfl_xor_sync(0xffffffffu, dotB, 1);

            const float hnA = fast_tanh(dotA + bi);
            const float hnB = fast_tanh(dotB + bi);

            // Hebbian updates
            fa0.x = l0.x * fa0.x + g0.x * hnA * za0.x;
            fa0.y = l0.y * fa0.y + g0.y * hnA * za0.y;
            fa0.z = l0.z * fa0.z + g0.z * hnA * za0.z;
            fa0.w = l0.w * fa0.w + g0.w * hnA * za0.w;
            fa1.x = l1.x * fa1.x + g1.x * hnA * za1.x;
            fa1.y = l1.y * fa1.y + g1.y * hnA * za1.y;
            fa1.z = l1.z * fa1.z + g1.z * hnA * za1.z;
            fa1.w = l1.w * fa1.w + g1.w * hnA * za1.w;
            fa2.x = l2.x * fa2.x + g2.x * hnA * za2.x;
            fa2.y = l2.y * fa2.y + g2.y * hnA * za2.y;
            fa2.z = l2.z * fa2.z + g2.z * hnA * za2.z;
            fa2.w = l2.w * fa2.w + g2.w * hnA * za2.w;

            fb0.x = l0.x * fb0.x + g0.x * hnB * zb0.x;
            fb0.y = l0.y * fb0.y + g0.y * hnB * zb0.y;
            fb0.z = l0.z * fb0.z + g0.z * hnB * zb0.z;
            fb0.w = l0.w * fb0.w + g0.w * hnB * zb0.w;
            fb1.x = l1.x * fb1.x + g1.x * hnB * zb1.x;
            fb1.y = l1.y * fb1.y + g1.y * hnB * zb1.y;
            fb1.z = l1.z * fb1.z + g1.z * hnB * zb1.z;
            fb1.w = l1.w * fb1.w + g1.w * hnB * zb1.w;
            fb2.x = l2.x * fb2.x + g2.x * hnB * zb2.x;
            fb2.y = l2.y * fb2.y + g2.y * hnB * zb2.y;
            fb2.z = l2.z * fb2.z + g2.z * hnB * zb2.z;
            fb2.w = l2.w * fb2.w + g2.w * hnB * zb2.w;

            float4* wa = Fw4 + (size_t)ja * FSTRIDE4;
            float4* wb = Fw4 + (size_t)jb * FSTRIDE4;
            wa[lane] = fa0; wa[lane + 32] = fa1; wa[lane + 64] = fa2;
            wb[lane] = fb0; wb[lane + 32] = fb1; wb[lane + 64] = fb2;

            if (lane == 0) {
                hw[(size_t)(b0 + ja) * HH + r] = hnA;
                hw[(size_t)(b0 + jb) * HH + r] = hnB;
                if (t == TT - 1) {
                    h_out[(size_t)(b0 + ja) * HH + r] = hnA;
                    h_out[(size_t)(b0 + jb) * HH + r] = hnB;
                }
            }
        }

        if (t == TT - 1) break;

        // ---- per-batch-group barrier (32 blocks share h for these batches) ----
        __threadfence();
        __syncthreads();
        if (tid == 0) {
            atomicAdd(ctr, 1u);
            const unsigned int target = (unsigned int)(t + 1) * NROWG;
            while (*((volatile unsigned int*)ctr) < target) {
                __nanosleep(32);
            }
        }
        __syncthreads();
    }
}

// tag_space = h_final @ W_out^T + b_out  — warp per (batch, output)
__global__ __launch_bounds__(128)
void tag_head_kernel(const float4* __restrict__ h4,    // [B,H]
                     const float4* __restrict__ Wout4, // [O,H]
                     const float*  __restrict__ bout,  // [O]
                     float* __restrict__ tag)          // [B,O]
{
    const int warp = threadIdx.x >> 5;
    const int lane = threadIdx.x & 31;
    const int o = blockIdx.x * 4 + warp;
    const int b = blockIdx.y;

    const float4* hr = h4    + (size_t)b * (HH / 4);
    const float4* wr = Wout4 + (size_t)o * (HH / 4);
    float4 hv0 = hr[lane], hv1 = hr[lane + 32];
    float4 wv0 = wr[lane], wv1 = wr[lane + 32];

    float dot = hv0.x * wv0.x + hv0.y * wv0.y + hv0.z * wv0.z + hv0.w * wv0.w
              + hv1.x * wv1.x + hv1.y * wv1.y + hv1.z * wv1.z + hv1.w * wv1.w;
    dot += __shfl_xor_sync(0xffffffffu, dot, 16);
    dot += __shfl_xor_sync(0xffffffffu, dot, 8);
    dot += __shfl_xor_sync(0xffffffffu, dot, 4);
    dot += __shfl_xor_sync(0xffffffffu, dot, 2);
    dot += __shfl_xor_sync(0xffffffffu, dot, 1);

    if (lane == 0) tag[(size_t)b * OO + o] = dot + bout[o];
}

extern "C" void kernel_launch(void* const* d_in, const int* in_sizes, int n_in,
                              void* d_out, int out_size)
{
    const float* x     = (const float*)d_in[0];  // sentence [B,T,D]
    const float* h0    = (const float*)d_in[1];  // [B,H]
    const float* F0    = (const float*)d_in[2];  // [B,H,Z]
    const float* W     = (const float*)d_in[3];  // [H,Z]
    const float* bias  = (const float*)d_in[4];  // [H]
    const float* lam   = (const float*)d_in[5];  // [H,Z]
    const float* gam   = (const float*)d_in[6];  // [H,Z]
    const float* Wout  = (const float*)d_in[7];  // [O,H]
    const float* bout  = (const float*)d_in[8];  // [O]

    // Output layout: concat(tag_space [B,O], h [B,H], F [B,H,Z])
    float* out   = (float*)d_out;
    float* tag   = out;
    float* h_out = out + (size_t)BATCH * OO;
    float* F_out = out + (size_t)BATCH * OO + (size_t)BATCH * HH;

    // Reset barrier counters (async memset is graph-capturable)
    void* bar_ptr = nullptr;
    cudaGetSymbolAddress(&bar_ptr, g_bar);
    cudaMemsetAsync(bar_ptr, 0, sizeof(unsigned int) * NBATG * 32);

    stpn_persistent<<<NBLOCKS, NTHREADS>>>(
        (const float4*)x, (const float4*)h0, F0, F_out,
        W, bias, lam, gam, h_out);

    dim3 tg(OO / 4, BATCH);
    tag_head_kernel<<<tg, 128>>>((const float4*)h_out, (const float4*)Wout,
                                 bout, tag);
}

// round 4
// speedup vs baseline: 1.4343x; 1.0392x over previous
#include <cuda_runtime.h>
#include <math.h>

// Problem constants (fixed shapes)
#define BATCH 128
#define TT    32
#define DD    128
#define HH    256
#define OO    128
#define ZZ    384   // D + H

#define NTHREADS 256
#define NWARPS   8     // rows per block (1 row per warp, fixed for all t)
#define NB       16    // batches per block
#define NRES     7     // SMEM-resident batches per warp
#define NROWG    32    // 256 rows / 8
#define NBATG    8     // 128 batches / 16
#define NBLOCKS  (NROWG * NBATG)   // 256 blocks; single wave (2/SM)

#define FSTRIDE4 ((HH * ZZ) / 4)   // float4 stride between batches in F

// Dynamic SMEM layout (float4 units):
//   [0 .. 16*96)                 : z staging, 16 batches x 96 float4
//   [1536 .. 1536 + 8*7*96)      : resident F tiles, warp-major
#define Z_F4     (NB * 96)                    // 1536
#define FSH_F4   (NWARPS * NRES * 96)         // 5376
#define SMEM_BYTES ((Z_F4 + FSH_F4) * 16)     // 110592

__device__ float g_hbuf[2][BATCH * HH];
__device__ unsigned int g_bar[NBATG * 32];

__device__ __forceinline__ float fast_tanh(float x) {
    float xc = fminf(fmaxf(x, -9.0f), 9.0f);
    float e  = __expf(2.0f * xc);
    return __fdividef(e - 1.0f, e + 1.0f);
}

__global__ __launch_bounds__(NTHREADS, 2)
void stpn_persistent(const float4* __restrict__ x4,   // [B,T,D]
                     const float4* __restrict__ h04,  // [B,H]
                     const float*  __restrict__ F0,   // [B,H,Z]
                     float* F_out,                    // [B,H,Z]
                     const float* __restrict__ W,     // [H,Z]
                     const float* __restrict__ bias,  // [H]
                     const float* __restrict__ lam,   // [H,Z]
                     const float* __restrict__ gam,   // [H,Z]
                     float* __restrict__ h_out)       // [B,H]
{
    extern __shared__ __align__(16) float4 smem[];
    float4* zsh4 = smem;            // [NB][96]
    float4* fsh  = smem + Z_F4;     // [NWARPS][NRES][96]

    const int tid  = threadIdx.x;
    const int warp = tid >> 5;
    const int lane = tid & 31;
    const int rowg = blockIdx.x & (NROWG - 1);
    const int batg = blockIdx.x >> 5;
    const int r    = rowg * NWARPS + warp;
    const int b0   = batg * NB;

    // Slow-weight parameters for this warp's row: loaded ONCE for the whole run
    const float4* Wr = reinterpret_cast<const float4*>(W   + (size_t)r * ZZ);
    const float4* Lr = reinterpret_cast<const float4*>(lam + (size_t)r * ZZ);
    const float4* Gr = reinterpret_cast<const float4*>(gam + (size_t)r * ZZ);
    const float4 w0 = Wr[lane], w1 = Wr[lane + 32], w2 = Wr[lane + 64];
    const float4 l0 = Lr[lane], l1 = Lr[lane + 32], l2 = Lr[lane + 64];
    const float4 g0 = Gr[lane], g1 = Gr[lane + 32], g2 = Gr[lane + 64];
    const float  bi = bias[r];

    const size_t fbase = ((size_t)b0 * HH + r) * (ZZ / 4);
    float4* Fw4 = reinterpret_cast<float4*>(F_out) + fbase;
    float4* myfsh = fsh + (size_t)(warp * NRES) * 96;

    // ---- prologue: preload resident batches (j = 0..NRES-1) from F0 ----
    {
        const float4* F04 = reinterpret_cast<const float4*>(F0) + fbase;
        #pragma unroll
        for (int js = 0; js < NRES; js++) {
            const float4* src = F04 + (size_t)js * FSTRIDE4;
            float4* dst = myfsh + js * 96;
            dst[lane] = src[lane];
            dst[lane + 32] = src[lane + 32];
            dst[lane + 64] = src[lane + 64];
        }
    }

    unsigned int* ctr = &g_bar[batg * 32];

    // fused cell for a pair of batches (in-place F update, returns h's)
    auto cell_pair = [&](float4& a0, float4& a1, float4& a2,
                         float4& b0v, float4& b1v, float4& b2v,
                         const float4* za, const float4* zb,
                         float& hnA, float& hnB,
                         float4& za0o, float4& za1o, float4& za2o,
                         float4& zb0o, float4& zb1o, float4& zb2o) {
        float4 za0 = za[lane], za1 = za[lane + 32], za2 = za[lane + 64];
        float4 zb0 = zb[lane], zb1 = zb[lane + 32], zb2 = zb[lane + 64];
        float dotA =
            (w0.x + a0.x) * za0.x + (w0.y + a0.y) * za0.y +
            (w0.z + a0.z) * za0.z + (w0.w + a0.w) * za0.w +
            (w1.x + a1.x) * za1.x + (w1.y + a1.y) * za1.y +
            (w1.z + a1.z) * za1.z + (w1.w + a1.w) * za1.w +
            (w2.x + a2.x) * za2.x + (w2.y + a2.y) * za2.y +
            (w2.z + a2.z) * za2.z + (w2.w + a2.w) * za2.w;
        float dotB =
            (w0.x + b0v.x) * zb0.x + (w0.y + b0v.y) * zb0.y +
            (w0.z + b0v.z) * zb0.z + (w0.w + b0v.w) * zb0.w +
            (w1.x + b1v.x) * zb1.x + (w1.y + b1v.y) * zb1.y +
            (w1.z + b1v.z) * zb1.z + (w1.w + b1v.w) * zb1.w +
            (w2.x + b2v.x) * zb2.x + (w2.y + b2v.y) * zb2.y +
            (w2.z + b2v.z) * zb2.z + (w2.w + b2v.w) * zb2.w;
        dotA += __shfl_xor_sync(0xffffffffu, dotA, 16);
        dotB += __shfl_xor_sync(0xffffffffu, dotB, 16);
        dotA += __shfl_xor_sync(0xffffffffu, dotA, 8);
        dotB += __shfl_xor_sync(0xffffffffu, dotB, 8);
        dotA += __shfl_xor_sync(0xffffffffu, dotA, 4);
        dotB += __shfl_xor_sync(0xffffffffu, dotB, 4);
        dotA += __shfl_xor_sync(0xffffffffu, dotA, 2);
        dotB += __shfl_xor_sync(0xffffffffu, dotB, 2);
        dotA += __shfl_xor_sync(0xffffffffu, dotA, 1);
        dotB += __shfl_xor_sync(0xffffffffu, dotB, 1);
        hnA = fast_tanh(dotA + bi);
        hnB = fast_tanh(dotB + bi);
        a0.x = l0.x * a0.x + g0.x * hnA * za0.x;
        a0.y = l0.y * a0.y + g0.y * hnA * za0.y;
        a0.z = l0.z * a0.z + g0.z * hnA * za0.z;
        a0.w = l0.w * a0.w + g0.w * hnA * za0.w;
        a1.x = l1.x * a1.x + g1.x * hnA * za1.x;
        a1.y = l1.y * a1.y + g1.y * hnA * za1.y;
        a1.z = l1.z * a1.z + g1.z * hnA * za1.z;
        a1.w = l1.w * a1.w + g1.w * hnA * za1.w;
        a2.x = l2.x * a2.x + g2.x * hnA * za2.x;
        a2.y = l2.y * a2.y + g2.y * hnA * za2.y;
        a2.z = l2.z * a2.z + g2.z * hnA * za2.z;
        a2.w = l2.w * a2.w + g2.w * hnA * za2.w;
        b0v.x = l0.x * b0v.x + g0.x * hnB * zb0.x;
        b0v.y = l0.y * b0v.y + g0.y * hnB * zb0.y;
        b0v.z = l0.z * b0v.z + g0.z * hnB * zb0.z;
        b0v.w = l0.w * b0v.w + g0.w * hnB * zb0.w;
        b1v.x = l1.x * b1v.x + g1.x * hnB * zb1.x;
        b1v.y = l1.y * b1v.y + g1.y * hnB * zb1.y;
        b1v.z = l1.z * b1v.z + g1.z * hnB * zb1.z;
        b1v.w = l1.w * b1v.w + g1.w * hnB * zb1.w;
        b2v.x = l2.x * b2v.x + g2.x * hnB * zb2.x;
        b2v.y = l2.y * b2v.y + g2.y * hnB * zb2.y;
        b2v.z = l2.z * b2v.z + g2.z * hnB * zb2.z;
        b2v.w = l2.w * b2v.w + g2.w * hnB * zb2.w;
        za0o = za0; za1o = za1; za2o = za2;
        zb0o = zb0; zb1o = zb1; zb2o = zb2;
    };

    for (int t = 0; t < TT; t++) {
        // ---- stage z = [x_t ; h_prev] ----
        for (int i = tid; i < NB * 32; i += NTHREADS) {
            int j = i >> 5, c = i & 31;
            zsh4[j * 96 + c] = x4[((size_t)(b0 + j) * TT + t) * 32 + c];
        }
        {
            const float4* hp4 = (t == 0) ? h04
                              : reinterpret_cast<const float4*>(g_hbuf[(t - 1) & 1]);
            for (int i = tid; i < NB * 64; i += NTHREADS) {
                int j = i >> 6, c = i & 63;
                zsh4[j * 96 + 32 + c] = __ldcg(&hp4[(size_t)(b0 + j) * 64 + c]);
            }
        }
        __syncthreads();

        const float4* Fr4 = (t == 0)
            ? reinterpret_cast<const float4*>(F0) + fbase
            : reinterpret_cast<const float4*>(F_out) + fbase;
        float* hw = g_hbuf[t & 1];
        const bool last = (t == TT - 1);

        // prefetch first streamed pair (j = NRES, NRES+1) — covers resident phase
        float4 pa0, pa1, pa2, pb0, pb1, pb2;
        {
            const float4* na = Fr4 + (size_t)NRES * FSTRIDE4;
            const float4* nb = Fr4 + (size_t)(NRES + 1) * FSTRIDE4;
            pa0 = na[lane]; pa1 = na[lane + 32]; pa2 = na[lane + 64];
            pb0 = nb[lane]; pb1 = nb[lane + 32]; pb2 = nb[lane + 64];
        }

        float4 zd0, zd1, zd2, zd3, zd4, zd5;   // dummies for z pass-out
        float hnA, hnB;

        // ---- resident batches (SMEM), pairs (0,1)(2,3)(4,5) + single 6 ----
        #pragma unroll
        for (int jp = 0; jp < (NRES - 1) / 2; jp++) {
            const int ja = 2 * jp, jb = ja + 1;
            float4* sa = myfsh + ja * 96;
            float4* sb = myfsh + jb * 96;
            float4 fa0 = sa[lane], fa1 = sa[lane + 32], fa2 = sa[lane + 64];
            float4 fb0 = sb[lane], fb1 = sb[lane + 32], fb2 = sb[lane + 64];
            cell_pair(fa0, fa1, fa2, fb0, fb1, fb2,
                      &zsh4[ja * 96], &zsh4[jb * 96], hnA, hnB,
                      zd0, zd1, zd2, zd3, zd4, zd5);
            sa[lane] = fa0; sa[lane + 32] = fa1; sa[lane + 64] = fa2;
            sb[lane] = fb0; sb[lane + 32] = fb1; sb[lane + 64] = fb2;
            if (last) {
                float4* wa = Fw4 + (size_t)ja * FSTRIDE4;
                float4* wb = Fw4 + (size_t)jb * FSTRIDE4;
                wa[lane] = fa0; wa[lane + 32] = fa1; wa[lane + 64] = fa2;
                wb[lane] = fb0; wb[lane + 32] = fb1; wb[lane + 64] = fb2;
            }
            if (lane == 0) {
                hw[(size_t)(b0 + ja) * HH + r] = hnA;
                hw[(size_t)(b0 + jb) * HH + r] = hnB;
                if (last) {
                    h_out[(size_t)(b0 + ja) * HH + r] = hnA;
                    h_out[(size_t)(b0 + jb) * HH + r] = hnB;
                }
            }
        }
        {   // resident single (j = NRES-1 = 6)
            const int js = NRES - 1;
            float4* sa = myfsh + js * 96;
            float4 f0 = sa[lane], f1 = sa[lane + 32], f2 = sa[lane + 64];
            const float4* zj = &zsh4[js * 96];
            float4 z0 = zj[lane], z1 = zj[lane + 32], z2 = zj[lane + 64];
            float dot =
                (w0.x + f0.x) * z0.x + (w0.y + f0.y) * z0.y +
                (w0.z + f0.z) * z0.z + (w0.w + f0.w) * z0.w +
                (w1.x + f1.x) * z1.x + (w1.y + f1.y) * z1.y +
                (w1.z + f1.z) * z1.z + (w1.w + f1.w) * z1.w +
                (w2.x + f2.x) * z2.x + (w2.y + f2.y) * z2.y +
                (w2.z + f2.z) * z2.z + (w2.w + f2.w) * z2.w;
            dot += __shfl_xor_sync(0xffffffffu, dot, 16);
            dot += __shfl_xor_sync(0xffffffffu, dot, 8);
            dot += __shfl_xor_sync(0xffffffffu, dot, 4);
            dot += __shfl_xor_sync(0xffffffffu, dot, 2);
            dot += __shfl_xor_sync(0xffffffffu, dot, 1);
            const float hn = fast_tanh(dot + bi);
            f0.x = l0.x * f0.x + g0.x * hn * z0.x;
            f0.y = l0.y * f0.y + g0.y * hn * z0.y;
            f0.z = l0.z * f0.z + g0.z * hn * z0.z;
            f0.w = l0.w * f0.w + g0.w * hn * z0.w;
            f1.x = l1.x * f1.x + g1.x * hn * z1.x;
            f1.y = l1.y * f1.y + g1.y * hn * z1.y;
            f1.z = l1.z * f1.z + g1.z * hn * z1.z;
            f1.w = l1.w * f1.w + g1.w * hn * z1.w;
            f2.x = l2.x * f2.x + g2.x * hn * z2.x;
            f2.y = l2.y * f2.y + g2.y * hn * z2.y;
            f2.z = l2.z * f2.z + g2.z * hn * z2.z;
            f2.w = l2.w * f2.w + g2.w * hn * z2.w;
            sa[lane] = f0; sa[lane + 32] = f1; sa[lane + 64] = f2;
            if (last) {
                float4* wa = Fw4 + (size_t)js * FSTRIDE4;
                wa[lane] = f0; wa[lane + 32] = f1; wa[lane + 64] = f2;
            }
            if (lane == 0) {
                hw[(size_t)(b0 + js) * HH + r] = hn;
                if (last) h_out[(size_t)(b0 + js) * HH + r] = hn;
            }
        }

        // ---- streamed batches j = NRES..15: 4 pairs + 1 single ----
        #pragma unroll 1
        for (int jp = 0; jp < 4; jp++) {
            const int ja = NRES + 2 * jp, jb = ja + 1;
            float4 fa0 = pa0, fa1 = pa1, fa2 = pa2;
            float4 fb0 = pb0, fb1 = pb1, fb2 = pb2;
            if (jp < 3) {   // prefetch next pair
                const float4* na = Fr4 + (size_t)(ja + 2) * FSTRIDE4;
                const float4* nb = Fr4 + (size_t)(jb + 2) * FSTRIDE4;
                pa0 = na[lane]; pa1 = na[lane + 32]; pa2 = na[lane + 64];
                pb0 = nb[lane]; pb1 = nb[lane + 32]; pb2 = nb[lane + 64];
            } else {        // prefetch final single (j = 15)
                const float4* na = Fr4 + (size_t)15 * FSTRIDE4;
                pa0 = na[lane]; pa1 = na[lane + 32]; pa2 = na[lane + 64];
            }
            cell_pair(fa0, fa1, fa2, fb0, fb1, fb2,
                      &zsh4[ja * 96], &zsh4[jb * 96], hnA, hnB,
                      zd0, zd1, zd2, zd3, zd4, zd5);
            float4* wa = Fw4 + (size_t)ja * FSTRIDE4;
            float4* wb = Fw4 + (size_t)jb * FSTRIDE4;
            wa[lane] = fa0; wa[lane + 32] = fa1; wa[lane + 64] = fa2;
            wb[lane] = fb0; wb[lane + 32] = fb1; wb[lane + 64] = fb2;
            if (lane == 0) {
                hw[(size_t)(b0 + ja) * HH + r] = hnA;
                hw[(size_t)(b0 + jb) * HH + r] = hnB;
                if (last) {
                    h_out[(size_t)(b0 + ja) * HH + r] = hnA;
                    h_out[(size_t)(b0 + jb) * HH + r] = hnB;
                }
            }
        }
        {   // streamed single (j = 15), data already prefetched in pa*
            const int js = 15;
            float4 f0 = pa0, f1 = pa1, f2 = pa2;
            const float4* zj = &zsh4[js * 96];
            float4 z0 = zj[lane], z1 = zj[lane + 32], z2 = zj[lane + 64];
            float dot =
                (w0.x + f0.x) * z0.x + (w0.y + f0.y) * z0.y +
                (w0.z + f0.z) * z0.z + (w0.w + f0.w) * z0.w +
                (w1.x + f1.x) * z1.x + (w1.y + f1.y) * z1.y +
                (w1.z + f1.z) * z1.z + (w1.w + f1.w) * z1.w +
                (w2.x + f2.x) * z2.x + (w2.y + f2.y) * z2.y +
                (w2.z + f2.z) * z2.z + (w2.w + f2.w) * z2.w;
            dot += __shfl_xor_sync(0xffffffffu, dot, 16);
            dot += __shfl_xor_sync(0xffffffffu, dot, 8);
            dot += __shfl_xor_sync(0xffffffffu, dot, 4);
            dot += __shfl_xor_sync(0xffffffffu, dot, 2);
            dot += __shfl_xor_sync(0xffffffffu, dot, 1);
            const float hn = fast_tanh(dot + bi);
            f0.x = l0.x * f0.x + g0.x * hn * z0.x;
            f0.y = l0.y * f0.y + g0.y * hn * z0.y;
            f0.z = l0.z * f0.z + g0.z * hn * z0.z;
            f0.w = l0.w * f0.w + g0.w * hn * z0.w;
            f1.x = l1.x * f1.x + g1.x * hn * z1.x;
            f1.y = l1.y * f1.y + g1.y * hn * z1.y;
            f1.z = l1.z * f1.z + g1.z * hn * z1.z;
            f1.w = l1.w * f1.w + g1.w * hn * z1.w;
            f2.x = l2.x * f2.x + g2.x * hn * z2.x;
            f2.y = l2.y * f2.y + g2.y * hn * z2.y;
            f2.z = l2.z * f2.z + g2.z * hn * z2.z;
            f2.w = l2.w * f2.w + g2.w * hn * z2.w;
            float4* wa = Fw4 + (size_t)js * FSTRIDE4;
            wa[lane] = f0; wa[lane + 32] = f1; wa[lane + 64] = f2;
            if (lane == 0) {
                hw[(size_t)(b0 + js) * HH + r] = hn;
                if (last) h_out[(size_t)(b0 + js) * HH + r] = hn;
            }
        }

        if (last) break;

        // ---- per-batch-group barrier (32 blocks share h for these batches) ----
        __threadfence();
        __syncthreads();
        if (tid == 0) {
            atomicAdd(ctr, 1u);
            const unsigned int target = (unsigned int)(t + 1) * NROWG;
            while (*((volatile unsigned int*)ctr) < target) {
                __nanosleep(32);
            }
        }
        __syncthreads();
    }
}

// tag_space = h_final @ W_out^T + b_out  — warp per (batch, output)
__global__ __launch_bounds__(128)
void tag_head_kernel(const float4* __restrict__ h4,    // [B,H]
                     const float4* __restrict__ Wout4, // [O,H]
                     const float*  __restrict__ bout,  // [O]
                     float* __restrict__ tag)          // [B,O]
{
    const int warp = threadIdx.x >> 5;
    const int lane = threadIdx.x & 31;
    const int o = blockIdx.x * 4 + warp;
    const int b = blockIdx.y;

    const float4* hr = h4    + (size_t)b * (HH / 4);
    const float4* wr = Wout4 + (size_t)o * (HH / 4);
    float4 hv0 = hr[lane], hv1 = hr[lane + 32];
    float4 wv0 = wr[lane], wv1 = wr[lane + 32];

    float dot = hv0.x * wv0.x + hv0.y * wv0.y + hv0.z * wv0.z + hv0.w * wv0.w
              + hv1.x * wv1.x + hv1.y * wv1.y + hv1.z * wv1.z + hv1.w * wv1.w;
    dot += __shfl_xor_sync(0xffffffffu, dot, 16);
    dot += __shfl_xor_sync(0xffffffffu, dot, 8);
    dot += __shfl_xor_sync(0xffffffffu, dot, 4);
    dot += __shfl_xor_sync(0xffffffffu, dot, 2);
    dot += __shfl_xor_sync(0xffffffffu, dot, 1);

    if (lane == 0) tag[(size_t)b * OO + o] = dot + bout[o];
}

extern "C" void kernel_launch(void* const* d_in, const int* in_sizes, int n_in,
                              void* d_out, int out_size)
{
    const float* x     = (const float*)d_in[0];
    const float* h0    = (const float*)d_in[1];
    const float* F0    = (const float*)d_in[2];
    const float* W     = (const float*)d_in[3];
    const float* bias  = (const float*)d_in[4];
    const float* lam   = (const float*)d_in[5];
    const float* gam   = (const float*)d_in[6];
    const float* Wout  = (const float*)d_in[7];
    const float* bout  = (const float*)d_in[8];

    // Output layout: concat(tag_space [B,O], h [B,H], F [B,H,Z])
    float* out   = (float*)d_out;
    float* tag   = out;
    float* h_out = out + (size_t)BATCH * OO;
    float* F_out = out + (size_t)BATCH * OO + (size_t)BATCH * HH;

    cudaFuncSetAttribute(stpn_persistent,
                         cudaFuncAttributeMaxDynamicSharedMemorySize, SMEM_BYTES);

    void* bar_ptr = nullptr;
    cudaGetSymbolAddress(&bar_ptr, g_bar);
    cudaMemsetAsync(bar_ptr, 0, sizeof(unsigned int) * NBATG * 32);

    stpn_persistent<<<NBLOCKS, NTHREADS, SMEM_BYTES>>>(
        (const float4*)x, (const float4*)h0, F0, F_out,
        W, bias, lam, gam, h_out);

    dim3 tg(OO / 4, BATCH);
    tag_head_kernel<<<tg, 128>>>((const float4*)h_out, (const float4*)Wout,
                                 bout, tag);
}